// round 10
// baseline (speedup 1.0000x reference)
#include <cuda_runtime.h>
#include <cuda_bf16.h>
#include <math.h>
#include <stdint.h>

#define B_  64
#define T_  512
#define D_  1024
#define NS_ (T_ / 128)          // s-tiles per row for score partials (=4)

// ---------------------------------------------------------------------------
// Device-global scratch (no allocation allowed)
// ---------------------------------------------------------------------------
__device__ __align__(16) __nv_bfloat16 g_xhi [(size_t)B_ * T_ * D_];
__device__ __align__(16) __nv_bfloat16 g_xlo [(size_t)B_ * T_ * D_];
__device__ __align__(16) __nv_bfloat16 g_wthi[(size_t)D_ * D_];   // W^T: [n][k]
__device__ __align__(16) __nv_bfloat16 g_wtlo[(size_t)D_ * D_];
__device__ __align__(16) __nv_bfloat16 g_xwhi[(size_t)B_ * T_ * D_];
__device__ __align__(16) __nv_bfloat16 g_xwlo[(size_t)B_ * T_ * D_];
__device__ float g_part[(size_t)B_ * T_ * NS_];
__device__ float g_a[(size_t)B_ * T_];
__device__ int   g_mask_is_byte;

__device__ __forceinline__ uint32_t smem_to_u32(const void* p) {
    uint32_t a;
    asm("{ .reg .u64 t; cvta.to.shared.u64 t, %1; cvt.u32.u64 %0, t; }"
        : "=r"(a) : "l"(p));
    return a;
}
__device__ __forceinline__ float fast_tanhf(float x) {
    float e = __expf(2.0f * x);
    return 1.0f - 2.0f / (e + 1.0f);
}
__device__ __forceinline__ uint32_t pack_bf16(float a, float b) {
    __nv_bfloat162 h = __floats2bfloat162_rn(a, b);
    return *(uint32_t*)&h;
}

// ---------------------------------------------------------------------------
// Tensor-core primitives (arch-agnostic: sm_80+ — valid on plain sm_103)
// ---------------------------------------------------------------------------
__device__ __forceinline__ void mma16816(float* c, const uint32_t* a, const uint32_t* b) {
    asm volatile("mma.sync.aligned.m16n8k16.row.col.f32.bf16.bf16.f32 "
                 "{%0,%1,%2,%3}, {%4,%5,%6,%7}, {%8,%9}, {%0,%1,%2,%3};"
                 : "+f"(c[0]), "+f"(c[1]), "+f"(c[2]), "+f"(c[3])
                 : "r"(a[0]), "r"(a[1]), "r"(a[2]), "r"(a[3]), "r"(b[0]), "r"(b[1]));
}
__device__ __forceinline__ void ldsm_x4(uint32_t* r, uint32_t addr) {
    asm volatile("ldmatrix.sync.aligned.m8n8.x4.shared.b16 {%0,%1,%2,%3}, [%4];"
                 : "=r"(r[0]), "=r"(r[1]), "=r"(r[2]), "=r"(r[3]) : "r"(addr));
}
__device__ __forceinline__ void cp_async16(uint32_t smem, const void* gmem) {
    asm volatile("cp.async.cg.shared.global [%0], [%1], 16;" :: "r"(smem), "l"(gmem));
}
#define CP_COMMIT()  asm volatile("cp.async.commit_group;" ::: "memory")
#define CP_WAIT(n)   asm volatile("cp.async.wait_group %0;" :: "n"(n) : "memory")

// ---------------------------------------------------------------------------
// Tile layout: 64(M) x 128(N) per CTA, 128 threads (4 warps, 2x2),
// 4 CTAs/SM. hi/lo merged side-by-side into 128B rows:
// row r = [HI(r,k0:32) | LO(r,k0:32)] = 8 x 16B chunks, chunk pc at physical
// (pc ^ (r&7)) -> conflict-free ldmatrix AND conflict-free cp.async stores.
// ---------------------------------------------------------------------------
#define OFF_A    0                 // A tile: 64 rows x 128B = 8 KB
#define OFF_B    8192              // B tile: 128 rows x 128B = 16 KB
#define BUF_SZ   24576
#define SM_TOTAL (2 * BUF_SZ)      // 48 KB dynamic (4 CTAs/SM = 192 KB)
#define STAGES   (D_ / 32)         // 32 (even)

// Load one merged ROWSx128B tile from hi/lo sources. 128 threads:
// pc = tid&7 fixed per thread -> loop-invariant source pointer.
template <int ROWS>
__device__ __forceinline__ void ld_tile(uint32_t sbase,
                                        const __nv_bfloat16* __restrict__ hiSrc,
                                        const __nv_bfloat16* __restrict__ loSrc,
                                        size_t row0, int k0, int tid) {
    const int pc = tid & 7;              // part = pc>>2, c = pc&3
    const int c  = pc & 3;
    const __nv_bfloat16* src = (pc >= 4) ? loSrc : hiSrc;
    #pragma unroll
    for (int i = 0; i < ROWS / 16; ++i) {
        int r = (tid >> 3) + 16 * i;
        cp_async16(sbase + r * 128 + ((pc ^ (r & 7)) << 4),
                   src + (row0 + r) * D_ + k0 + c * 8);
    }
}

__device__ __forceinline__ void ld_stage(uint32_t sbuf,
                                         const __nv_bfloat16* aHi, const __nv_bfloat16* aLo,
                                         const __nv_bfloat16* bHi, const __nv_bfloat16* bLo,
                                         size_t arow0, size_t brow0, int k0, int tid) {
    ld_tile<64>(sbuf + OFF_A, aHi, aLo, arow0, k0, tid);
    ld_tile<128>(sbuf + OFF_B, bHi, bLo, brow0, k0, tid);
    CP_COMMIT();
}

// ldmatrix address: 16x16 frag (4 8x8 matrices) at (rowbase, logical pcbase).
__device__ __forceinline__ uint32_t frag_addr(uint32_t base, int rowbase, int pcbase, int lane) {
    int grp = lane >> 3, rin = lane & 7;
    int row = rowbase + ((grp & 1) << 3) + rin;
    int pc  = pcbase + (grp >> 1);
    return base + row * 128 + ((pc ^ (row & 7)) << 4);
}

// One stage (K=32) of 3-product split MMA into acc[2][8][4].
// Warp tile 32(M) x 64(N): mf<2, nf<8.
__device__ __forceinline__ void stage_mma(float acc[2][8][4], uint32_t sbuf,
                                          int warp_m, int warp_n, int lane) {
    #pragma unroll
    for (int ks = 0; ks < 2; ++ks) {
        uint32_t ahi[2][4], alo[2][4];
        #pragma unroll
        for (int mf = 0; mf < 2; ++mf) {
            ldsm_x4(ahi[mf], frag_addr(sbuf + OFF_A, warp_m * 32 + mf * 16, ks * 2,     lane));
            ldsm_x4(alo[mf], frag_addr(sbuf + OFF_A, warp_m * 32 + mf * 16, 4 + ks * 2, lane));
        }
        uint32_t bhi[8][2], blo[8][2];
        #pragma unroll
        for (int p = 0; p < 4; ++p) {
            uint32_t r[4];
            ldsm_x4(r, frag_addr(sbuf + OFF_B, warp_n * 64 + p * 16, ks * 2, lane));
            bhi[2*p][0] = r[0]; bhi[2*p][1] = r[2];
            bhi[2*p+1][0] = r[1]; bhi[2*p+1][1] = r[3];
            ldsm_x4(r, frag_addr(sbuf + OFF_B, warp_n * 64 + p * 16, 4 + ks * 2, lane));
            blo[2*p][0] = r[0]; blo[2*p][1] = r[2];
            blo[2*p+1][0] = r[1]; blo[2*p+1][1] = r[3];
        }
        #pragma unroll
        for (int mf = 0; mf < 2; ++mf)
            #pragma unroll
            for (int nf = 0; nf < 8; ++nf)
                mma16816(acc[mf][nf], ahi[mf], bhi[nf]);
        #pragma unroll
        for (int mf = 0; mf < 2; ++mf)
            #pragma unroll
            for (int nf = 0; nf < 8; ++nf)
                mma16816(acc[mf][nf], ahi[mf], blo[nf]);
        #pragma unroll
        for (int mf = 0; mf < 2; ++mf)
            #pragma unroll
            for (int nf = 0; nf < 8; ++nf)
                mma16816(acc[mf][nf], alo[mf], bhi[nf]);
    }
}

// Pipelined mainloop: double buffer, ONE __syncthreads per stage.
__device__ __forceinline__ void gemm_mainloop(float acc[2][8][4], uint32_t sbase,
                                              const __nv_bfloat16* aHi, const __nv_bfloat16* aLo,
                                              const __nv_bfloat16* bHi, const __nv_bfloat16* bLo,
                                              size_t arow0, size_t brow0,
                                              int tid, int warp_m, int warp_n, int lane) {
    const uint32_t buf0 = sbase, buf1 = sbase + BUF_SZ;
    ld_stage(buf0, aHi, aLo, bHi, bLo, arow0, brow0, 0, tid);
    #pragma unroll 1
    for (int s = 0; s < STAGES; s += 2) {
        CP_WAIT(0);
        __syncthreads();
        ld_stage(buf1, aHi, aLo, bHi, bLo, arow0, brow0, (s + 1) * 32, tid);
        stage_mma(acc, buf0, warp_m, warp_n, lane);
        CP_WAIT(0);
        __syncthreads();
        if (s + 2 < STAGES)
            ld_stage(buf0, aHi, aLo, bHi, bLo, arow0, brow0, (s + 2) * 32, tid);
        stage_mma(acc, buf1, warp_m, warp_n, lane);
    }
}

// ---------------------------------------------------------------------------
// Kernel 0: mask dtype detection (byte-bool vs int32)
// ---------------------------------------------------------------------------
__global__ void k_detect(const unsigned char* __restrict__ m) {
    __shared__ int found;
    if (threadIdx.x == 0) found = 0;
    __syncthreads();
    int f = 0;
    for (int i = threadIdx.x; i < B_ * T_; i += blockDim.x)
        if ((i & 3) != 0 && m[i] != 0) f = 1;
    if (f) atomicOr(&found, 1);
    __syncthreads();
    if (threadIdx.x == 0) g_mask_is_byte = found;
}

// ---------------------------------------------------------------------------
// Split x into bf16 hi/lo (4 floats per thread, vectorized).
// ---------------------------------------------------------------------------
__global__ __launch_bounds__(256) void k_split_x(const float* __restrict__ x) {
    size_t idx = (size_t)blockIdx.x * blockDim.x + threadIdx.x;
    float4 v = ((const float4*)x)[idx];
    float h0 = __bfloat162float(__float2bfloat16_rn(v.x));
    float h1 = __bfloat162float(__float2bfloat16_rn(v.y));
    float h2 = __bfloat162float(__float2bfloat16_rn(v.z));
    float h3 = __bfloat162float(__float2bfloat16_rn(v.w));
    ((uint2*)g_xhi)[idx] = make_uint2(pack_bf16(h0, h1), pack_bf16(h2, h3));
    ((uint2*)g_xlo)[idx] = make_uint2(pack_bf16(v.x - h0, v.y - h1),
                                      pack_bf16(v.z - h2, v.w - h3));
}

// ---------------------------------------------------------------------------
// Split + transpose W: g_wt*[n*D + k] = split(W[k*D + n])
// ---------------------------------------------------------------------------
__global__ __launch_bounds__(1024) void k_split_wt(const float* __restrict__ w) {
    __shared__ float t[32][33];
    int tx = threadIdx.x & 31, ty = threadIdx.x >> 5;
    int k = blockIdx.y * 32 + ty, n = blockIdx.x * 32 + tx;
    t[ty][tx] = w[(size_t)k * D_ + n];
    __syncthreads();
    float v = t[tx][ty];  // = W[by*32+tx][bx*32+ty]
    int nn = blockIdx.x * 32 + ty, kk = blockIdx.y * 32 + tx;
    float h = __bfloat162float(__float2bfloat16_rn(v));
    g_wthi[(size_t)nn * D_ + kk] = __float2bfloat16_rn(v);
    g_wtlo[(size_t)nn * D_ + kk] = __float2bfloat16_rn(v - h);
}

// ---------------------------------------------------------------------------
// Kernel 1: xw = x @ W. Tile 64(M)x128(N), grid (D/128, B*T/64), 128 threads,
// 4 CTAs/SM pinned via __launch_bounds__(128, 4).
// ---------------------------------------------------------------------------
__global__ __launch_bounds__(128, 4) void k_xw_tc() {
    extern __shared__ char sm[];
    const uint32_t sbase = smem_to_u32(sm);
    const int tid = threadIdx.x, lane = tid & 31, wid = tid >> 5;
    const int warp_m = wid & 1, warp_n = wid >> 1;
    const size_t m0 = (size_t)blockIdx.y * 64;
    const size_t n0 = (size_t)blockIdx.x * 128;

    float acc[2][8][4] = {};
    gemm_mainloop(acc, sbase, g_xhi, g_xlo, g_wthi, g_wtlo,
                  m0, n0, tid, warp_m, warp_n, lane);

    #pragma unroll
    for (int mf = 0; mf < 2; ++mf) {
        size_t r0 = m0 + warp_m * 32 + mf * 16 + (lane >> 2);
        #pragma unroll
        for (int nf = 0; nf < 8; ++nf) {
            size_t c = n0 + warp_n * 64 + nf * 8 + (lane & 3) * 2;
            float v0 = acc[mf][nf][0], v1 = acc[mf][nf][1];
            float v2 = acc[mf][nf][2], v3 = acc[mf][nf][3];
            float h0 = __bfloat162float(__float2bfloat16_rn(v0));
            float h1 = __bfloat162float(__float2bfloat16_rn(v1));
            float h2 = __bfloat162float(__float2bfloat16_rn(v2));
            float h3 = __bfloat162float(__float2bfloat16_rn(v3));
            *(uint32_t*)(g_xwhi + r0 * D_ + c)       = pack_bf16(h0, h1);
            *(uint32_t*)(g_xwlo + r0 * D_ + c)       = pack_bf16(v0 - h0, v1 - h1);
            *(uint32_t*)(g_xwhi + (r0 + 8) * D_ + c) = pack_bf16(h2, h3);
            *(uint32_t*)(g_xwlo + (r0 + 8) * D_ + c) = pack_bf16(v2 - h2, v3 - h3);
        }
    }
}

// ---------------------------------------------------------------------------
// Kernel 2: eij tile = xw_b[t0:+64] @ x_b[s0:+128]^T with fused
// cv*tanh(e+bias) reduction over s. grid (T/128, T/64, B), 128 threads.
// ---------------------------------------------------------------------------
__global__ __launch_bounds__(128, 4) void k_scores_tc(const float* __restrict__ cv,
                                                      const float* __restrict__ bias) {
    extern __shared__ char sm[];
    const uint32_t sbase = smem_to_u32(sm);
    const int tid = threadIdx.x, lane = tid & 31, wid = tid >> 5;
    const int warp_m = wid & 1, warp_n = wid >> 1;
    const int b = blockIdx.z, t0 = blockIdx.y * 64, s0 = blockIdx.x * 128;
    const size_t boff = (size_t)b * T_;

    float acc[2][8][4] = {};
    gemm_mainloop(acc, sbase, g_xwhi, g_xwlo, g_xhi, g_xlo,
                  boff + t0, boff + s0, tid, warp_m, warp_n, lane);

    // Per-lane cv/bias for its 16 s-columns
    float cvv[16], bsv[16];
    #pragma unroll
    for (int nf = 0; nf < 8; ++nf)
        #pragma unroll
        for (int e = 0; e < 2; ++e) {
            int c = s0 + warp_n * 64 + nf * 8 + (lane & 3) * 2 + e;
            cvv[nf * 2 + e] = cv[c];
            bsv[nf * 2 + e] = bias[c];
        }

    // Reduction staging at base of smem (all buffers dead after last barrier
    // + final stage_mma read of buf1; writes land in buf0's region).
    float* red = (float*)sm;   // [64][2]
    #pragma unroll
    for (int mf = 0; mf < 2; ++mf) {
        float p0 = 0.0f, p1 = 0.0f;
        #pragma unroll
        for (int nf = 0; nf < 8; ++nf)
            #pragma unroll
            for (int e = 0; e < 2; ++e) {
                p0 += cvv[nf*2+e] * fast_tanhf(acc[mf][nf][e]     + bsv[nf*2+e]);
                p1 += cvv[nf*2+e] * fast_tanhf(acc[mf][nf][2 + e] + bsv[nf*2+e]);
            }
        // reduce across the 4 lanes sharing a row
        p0 += __shfl_xor_sync(0xffffffffu, p0, 1);
        p0 += __shfl_xor_sync(0xffffffffu, p0, 2);
        p1 += __shfl_xor_sync(0xffffffffu, p1, 1);
        p1 += __shfl_xor_sync(0xffffffffu, p1, 2);
        if ((lane & 3) == 0) {
            int r = warp_m * 32 + mf * 16 + (lane >> 2);
            red[r * 2 + warp_n]       = p0;
            red[(r + 8) * 2 + warp_n] = p1;
        }
    }
    __syncthreads();
    if (tid < 64) {
        float s = red[tid * 2] + red[tid * 2 + 1];
        g_part[(boff + t0 + tid) * NS_ + blockIdx.x] = s;
    }
}

// ---------------------------------------------------------------------------
// Kernel 3: masked softmax over T per batch. grid = B, block = T.
// ---------------------------------------------------------------------------
__global__ __launch_bounds__(T_) void k_softmax(const unsigned char* __restrict__ mask,
                                                float* __restrict__ a_out) {
    const int b = blockIdx.x;
    const int t = threadIdx.x;
    __shared__ float sh[T_];

    float sc = 0.0f;
    #pragma unroll
    for (int j = 0; j < NS_; ++j)
        sc += g_part[((size_t)b * T_ + t) * NS_ + j];

    bool m;
    if (g_mask_is_byte) m = mask[(size_t)b * T_ + t] != 0;
    else                m = ((const int*)mask)[(size_t)b * T_ + t] != 0;

    const float NEG_INF = __int_as_float(0xff800000);
    float v = m ? sc : NEG_INF;

    sh[t] = v; __syncthreads();
    for (int off = T_ / 2; off > 0; off >>= 1) {
        if (t < off) sh[t] = fmaxf(sh[t], sh[t + off]);
        __syncthreads();
    }
    const float mx = sh[0];
    __syncthreads();

    float e = m ? expf(v - mx) : 0.0f;
    sh[t] = e; __syncthreads();
    for (int off = T_ / 2; off > 0; off >>= 1) {
        if (t < off) sh[t] += sh[t + off];
        __syncthreads();
    }
    float av = e * (1.0f / sh[0]);
    g_a[(size_t)b * T_ + t] = av;
    if (a_out) a_out[(size_t)b * T_ + t] = av;
}

// ---------------------------------------------------------------------------
// Kernel 4: out[b,d] = sum_t a[b,t] * x[b,t,d]
// ---------------------------------------------------------------------------
__global__ __launch_bounds__(128) void k_out(const float* __restrict__ x,
                                             float* __restrict__ out) {
    const int b = blockIdx.y;
    const int d = blockIdx.x * 128 + threadIdx.x;
    __shared__ float sa[T_];
    for (int t = threadIdx.x; t < T_; t += 128)
        sa[t] = g_a[(size_t)b * T_ + t];
    __syncthreads();

    float acc = 0.0f;
    const float* xb = x + (size_t)b * T_ * D_ + d;
    #pragma unroll 8
    for (int t = 0; t < T_; ++t)
        acc += sa[t] * xb[(size_t)t * D_];
    out[(size_t)b * D_ + d] = acc;
}

// ---------------------------------------------------------------------------
extern "C" void kernel_launch(void* const* d_in, const int* in_sizes, int n_in,
                              void* d_out, int out_size) {
    const float*         x    = (const float*)d_in[0];
    const unsigned char* mask = (const unsigned char*)d_in[1];
    const float*         w    = (const float*)d_in[2];
    const float*         cv   = (const float*)d_in[3];
    const float*         bias = (const float*)d_in[4];
    float* out = (float*)d_out;
    float* a_out = (out_size >= B_ * D_ + B_ * T_) ? out + (size_t)B_ * D_ : nullptr;

    cudaFuncSetAttribute(k_xw_tc,     cudaFuncAttributeMaxDynamicSharedMemorySize, SM_TOTAL);
    cudaFuncSetAttribute(k_scores_tc, cudaFuncAttributeMaxDynamicSharedMemorySize, SM_TOTAL);

    k_detect   <<<1, 1024>>>(mask);
    k_split_x  <<<(B_ * T_ * D_) / (4 * 256), 256>>>(x);
    k_split_wt <<<dim3(D_ / 32, D_ / 32), 1024>>>(w);
    k_xw_tc    <<<dim3(D_ / 128, (B_ * T_) / 64), 128, SM_TOTAL>>>();
    k_scores_tc<<<dim3(T_ / 128, T_ / 64, B_), 128, SM_TOTAL>>>(cv, bias);
    k_softmax  <<<B_, T_>>>(mask, a_out);
    k_out      <<<dim3(D_ / 128, B_), 128>>>(x, out);
}

// round 11
// speedup vs baseline: 1.3099x; 1.3099x over previous
#include <cuda_runtime.h>
#include <cuda_bf16.h>
#include <math.h>
#include <stdint.h>

#define B_  64
#define T_  512
#define D_  1024
#define NS_ (T_ / 128)          // s-tiles per row for score partials (=4)

// ---------------------------------------------------------------------------
// Device-global scratch (no allocation allowed)
// ---------------------------------------------------------------------------
__device__ __align__(16) __nv_bfloat16 g_xhi [(size_t)B_ * T_ * D_];
__device__ __align__(16) __nv_bfloat16 g_xlo [(size_t)B_ * T_ * D_];
__device__ __align__(16) __nv_bfloat16 g_wthi[(size_t)D_ * D_];   // W^T: [n][k]
__device__ __align__(16) __nv_bfloat16 g_wtlo[(size_t)D_ * D_];
__device__ __align__(16) __nv_bfloat16 g_xwhi[(size_t)B_ * T_ * D_];
__device__ __align__(16) __nv_bfloat16 g_xwlo[(size_t)B_ * T_ * D_];
__device__ float g_part[(size_t)B_ * T_ * NS_];
__device__ float g_a[(size_t)B_ * T_];
__device__ int   g_mask_is_byte;

__device__ __forceinline__ uint32_t smem_to_u32(const void* p) {
    uint32_t a;
    asm("{ .reg .u64 t; cvta.to.shared.u64 t, %1; cvt.u32.u64 %0, t; }"
        : "=r"(a) : "l"(p));
    return a;
}
__device__ __forceinline__ float fast_tanhf(float x) {
    float e = __expf(2.0f * x);
    return 1.0f - 2.0f / (e + 1.0f);
}
__device__ __forceinline__ uint32_t pack_bf16(float a, float b) {
    __nv_bfloat162 h = __floats2bfloat162_rn(a, b);
    return *(uint32_t*)&h;
}

// ---------------------------------------------------------------------------
// Tensor-core primitives (arch-agnostic: sm_80+ — valid on plain sm_103)
// ---------------------------------------------------------------------------
__device__ __forceinline__ void mma16816(float* c, const uint32_t* a, const uint32_t* b) {
    asm volatile("mma.sync.aligned.m16n8k16.row.col.f32.bf16.bf16.f32 "
                 "{%0,%1,%2,%3}, {%4,%5,%6,%7}, {%8,%9}, {%0,%1,%2,%3};"
                 : "+f"(c[0]), "+f"(c[1]), "+f"(c[2]), "+f"(c[3])
                 : "r"(a[0]), "r"(a[1]), "r"(a[2]), "r"(a[3]), "r"(b[0]), "r"(b[1]));
}
__device__ __forceinline__ void ldsm_x4(uint32_t* r, uint32_t addr) {
    asm volatile("ldmatrix.sync.aligned.m8n8.x4.shared.b16 {%0,%1,%2,%3}, [%4];"
                 : "=r"(r[0]), "=r"(r[1]), "=r"(r[2]), "=r"(r[3]) : "r"(addr));
}
__device__ __forceinline__ void cp_async16(uint32_t smem, const void* gmem) {
    asm volatile("cp.async.cg.shared.global [%0], [%1], 16;" :: "r"(smem), "l"(gmem));
}
#define CP_COMMIT()  asm volatile("cp.async.commit_group;" ::: "memory")
#define CP_WAIT(n)   asm volatile("cp.async.wait_group %0;" :: "n"(n) : "memory")

// ---------------------------------------------------------------------------
// Tile: 256(M) x 128(N) per CTA, 512 threads (16 warps, 4x4), 1 CTA/SM.
// hi/lo merged side-by-side into 128B rows: row r = [HI(r,k0:32)|LO(r,k0:32)]
// = 8 x 16B chunks; chunk pc lives at physical (pc ^ (r&7)) -> conflict-free
// ldmatrix AND conflict-free cp.async stores. 4 buffers, 2 load-stages in
// flight (CP_WAIT(2)) to hide L2 delivery latency/jitter.
// ---------------------------------------------------------------------------
#define OFF_A    0                 // A tile: 256 rows x 128B = 32 KB
#define OFF_B    32768             // B tile: 128 rows x 128B = 16 KB
#define BUF_SZ   49152
#define NBUF     4
#define SM_TOTAL (NBUF * BUF_SZ)   // 192 KB dynamic, 1 CTA/SM
#define STAGES   (D_ / 32)         // 32

// Load one merged ROWSx128B tile from hi/lo sources. 512 threads:
// pc = tid&7 fixed per thread -> loop-invariant source pointer.
template <int ROWS>
__device__ __forceinline__ void ld_tile(uint32_t sbase,
                                        const __nv_bfloat16* __restrict__ hiSrc,
                                        const __nv_bfloat16* __restrict__ loSrc,
                                        size_t row0, int k0, int tid) {
    const int pc = tid & 7;              // part = pc>>2, c = pc&3
    const int c  = pc & 3;
    const __nv_bfloat16* src = (pc >= 4) ? loSrc : hiSrc;
    #pragma unroll
    for (int i = 0; i < ROWS / 64; ++i) {
        int r = (tid >> 3) + 64 * i;
        cp_async16(sbase + r * 128 + ((pc ^ (r & 7)) << 4),
                   src + (row0 + r) * D_ + k0 + c * 8);
    }
}

__device__ __forceinline__ void ld_stage(uint32_t sbuf,
                                         const __nv_bfloat16* aHi, const __nv_bfloat16* aLo,
                                         const __nv_bfloat16* bHi, const __nv_bfloat16* bLo,
                                         size_t arow0, size_t brow0, int k0, int tid) {
    ld_tile<256>(sbuf + OFF_A, aHi, aLo, arow0, k0, tid);
    ld_tile<128>(sbuf + OFF_B, bHi, bLo, brow0, k0, tid);
    CP_COMMIT();
}

// ldmatrix address: 16x16 frag (4 8x8 matrices) at (rowbase, logical pcbase).
__device__ __forceinline__ uint32_t frag_addr(uint32_t base, int rowbase, int pcbase, int lane) {
    int grp = lane >> 3, rin = lane & 7;
    int row = rowbase + ((grp & 1) << 3) + rin;
    int pc  = pcbase + (grp >> 1);
    return base + row * 128 + ((pc ^ (row & 7)) << 4);
}

// One stage (K=32) of 3-product split MMA into acc[4][4][4].
// Warp tile 64(M) x 32(N): identical to the R9 kernel's inner machinery.
__device__ __forceinline__ void stage_mma(float acc[4][4][4], uint32_t sbuf,
                                          int warp_m, int warp_n, int lane) {
    #pragma unroll
    for (int ks = 0; ks < 2; ++ks) {
        uint32_t ahi[4][4], alo[4][4];
        #pragma unroll
        for (int mf = 0; mf < 4; ++mf) {
            ldsm_x4(ahi[mf], frag_addr(sbuf + OFF_A, warp_m * 64 + mf * 16, ks * 2,     lane));
            ldsm_x4(alo[mf], frag_addr(sbuf + OFF_A, warp_m * 64 + mf * 16, 4 + ks * 2, lane));
        }
        uint32_t bhi[4][2], blo[4][2];
        #pragma unroll
        for (int p = 0; p < 2; ++p) {
            uint32_t r[4];
            ldsm_x4(r, frag_addr(sbuf + OFF_B, warp_n * 32 + p * 16, ks * 2, lane));
            bhi[2*p][0] = r[0]; bhi[2*p][1] = r[2];
            bhi[2*p+1][0] = r[1]; bhi[2*p+1][1] = r[3];
            ldsm_x4(r, frag_addr(sbuf + OFF_B, warp_n * 32 + p * 16, 4 + ks * 2, lane));
            blo[2*p][0] = r[0]; blo[2*p][1] = r[2];
            blo[2*p+1][0] = r[1]; blo[2*p+1][1] = r[3];
        }
        #pragma unroll
        for (int mf = 0; mf < 4; ++mf)
            #pragma unroll
            for (int nf = 0; nf < 4; ++nf)
                mma16816(acc[mf][nf], ahi[mf], bhi[nf]);
        #pragma unroll
        for (int mf = 0; mf < 4; ++mf)
            #pragma unroll
            for (int nf = 0; nf < 4; ++nf)
                mma16816(acc[mf][nf], ahi[mf], blo[nf]);
        #pragma unroll
        for (int mf = 0; mf < 4; ++mf)
            #pragma unroll
            for (int nf = 0; nf < 4; ++nf)
                mma16816(acc[mf][nf], alo[mf], bhi[nf]);
    }
}

// Mainloop: 4 buffers, 2 load-stages in flight, ONE __syncthreads per stage.
// Stage s: wait(group s done; keep s+1,s+2 in flight) -> barrier (all warps
// past mma(s-1), the only reader of buf (s+3)&3) -> issue loads(s+3) -> mma(s).
__device__ __forceinline__ void gemm_mainloop(float acc[4][4][4], uint32_t sbase,
                                              const __nv_bfloat16* aHi, const __nv_bfloat16* aLo,
                                              const __nv_bfloat16* bHi, const __nv_bfloat16* bLo,
                                              size_t arow0, size_t brow0,
                                              int tid, int warp_m, int warp_n, int lane) {
    ld_stage(sbase + 0 * BUF_SZ, aHi, aLo, bHi, bLo, arow0, brow0, 0,  tid);
    ld_stage(sbase + 1 * BUF_SZ, aHi, aLo, bHi, bLo, arow0, brow0, 32, tid);
    ld_stage(sbase + 2 * BUF_SZ, aHi, aLo, bHi, bLo, arow0, brow0, 64, tid);
    #pragma unroll 1
    for (int s = 0; s < STAGES; ++s) {
        if (s < STAGES - 3) { CP_WAIT(2); } else { CP_WAIT(0); }
        __syncthreads();
        if (s + 3 < STAGES)
            ld_stage(sbase + ((s + 3) & 3) * BUF_SZ, aHi, aLo, bHi, bLo,
                     arow0, brow0, (s + 3) * 32, tid);
        stage_mma(acc, sbase + (s & 3) * BUF_SZ, warp_m, warp_n, lane);
    }
}

// ---------------------------------------------------------------------------
// Kernel 0: mask dtype detection (byte-bool vs int32)
// ---------------------------------------------------------------------------
__global__ void k_detect(const unsigned char* __restrict__ m) {
    __shared__ int found;
    if (threadIdx.x == 0) found = 0;
    __syncthreads();
    int f = 0;
    for (int i = threadIdx.x; i < B_ * T_; i += blockDim.x)
        if ((i & 3) != 0 && m[i] != 0) f = 1;
    if (f) atomicOr(&found, 1);
    __syncthreads();
    if (threadIdx.x == 0) g_mask_is_byte = found;
}

// ---------------------------------------------------------------------------
// Split x into bf16 hi/lo (4 floats per thread, vectorized).
// ---------------------------------------------------------------------------
__global__ __launch_bounds__(256) void k_split_x(const float* __restrict__ x) {
    size_t idx = (size_t)blockIdx.x * blockDim.x + threadIdx.x;
    float4 v = ((const float4*)x)[idx];
    float h0 = __bfloat162float(__float2bfloat16_rn(v.x));
    float h1 = __bfloat162float(__float2bfloat16_rn(v.y));
    float h2 = __bfloat162float(__float2bfloat16_rn(v.z));
    float h3 = __bfloat162float(__float2bfloat16_rn(v.w));
    ((uint2*)g_xhi)[idx] = make_uint2(pack_bf16(h0, h1), pack_bf16(h2, h3));
    ((uint2*)g_xlo)[idx] = make_uint2(pack_bf16(v.x - h0, v.y - h1),
                                      pack_bf16(v.z - h2, v.w - h3));
}

// ---------------------------------------------------------------------------
// Split + transpose W: g_wt*[n*D + k] = split(W[k*D + n])
// ---------------------------------------------------------------------------
__global__ __launch_bounds__(1024) void k_split_wt(const float* __restrict__ w) {
    __shared__ float t[32][33];
    int tx = threadIdx.x & 31, ty = threadIdx.x >> 5;
    int k = blockIdx.y * 32 + ty, n = blockIdx.x * 32 + tx;
    t[ty][tx] = w[(size_t)k * D_ + n];
    __syncthreads();
    float v = t[tx][ty];  // = W[by*32+tx][bx*32+ty]
    int nn = blockIdx.x * 32 + ty, kk = blockIdx.y * 32 + tx;
    float h = __bfloat162float(__float2bfloat16_rn(v));
    g_wthi[(size_t)nn * D_ + kk] = __float2bfloat16_rn(v);
    g_wtlo[(size_t)nn * D_ + kk] = __float2bfloat16_rn(v - h);
}

// ---------------------------------------------------------------------------
// Kernel 1: xw = x @ W. Tile 256(M)x128(N), grid (D/128, B*T/256),
// 512 threads, 1 CTA/SM pinned via __launch_bounds__(512, 1).
// ---------------------------------------------------------------------------
__global__ __launch_bounds__(512, 1) void k_xw_tc() {
    extern __shared__ char sm[];
    const uint32_t sbase = smem_to_u32(sm);
    const int tid = threadIdx.x, lane = tid & 31, wid = tid >> 5;
    const int warp_m = wid & 3, warp_n = wid >> 2;
    const size_t m0 = (size_t)blockIdx.y * 256;
    const size_t n0 = (size_t)blockIdx.x * 128;

    float acc[4][4][4] = {};
    gemm_mainloop(acc, sbase, g_xhi, g_xlo, g_wthi, g_wtlo,
                  m0, n0, tid, warp_m, warp_n, lane);

    #pragma unroll
    for (int mf = 0; mf < 4; ++mf) {
        size_t r0 = m0 + warp_m * 64 + mf * 16 + (lane >> 2);
        #pragma unroll
        for (int nf = 0; nf < 4; ++nf) {
            size_t c = n0 + warp_n * 32 + nf * 8 + (lane & 3) * 2;
            float v0 = acc[mf][nf][0], v1 = acc[mf][nf][1];
            float v2 = acc[mf][nf][2], v3 = acc[mf][nf][3];
            float h0 = __bfloat162float(__float2bfloat16_rn(v0));
            float h1 = __bfloat162float(__float2bfloat16_rn(v1));
            float h2 = __bfloat162float(__float2bfloat16_rn(v2));
            float h3 = __bfloat162float(__float2bfloat16_rn(v3));
            *(uint32_t*)(g_xwhi + r0 * D_ + c)       = pack_bf16(h0, h1);
            *(uint32_t*)(g_xwlo + r0 * D_ + c)       = pack_bf16(v0 - h0, v1 - h1);
            *(uint32_t*)(g_xwhi + (r0 + 8) * D_ + c) = pack_bf16(h2, h3);
            *(uint32_t*)(g_xwlo + (r0 + 8) * D_ + c) = pack_bf16(v2 - h2, v3 - h3);
        }
    }
}

// ---------------------------------------------------------------------------
// Kernel 2: eij tile = xw_b[t0:+256] @ x_b[s0:+128]^T with fused
// cv*tanh(e+bias) reduction over s. grid (T/128, T/256, B), 512 threads.
// ---------------------------------------------------------------------------
__global__ __launch_bounds__(512, 1) void k_scores_tc(const float* __restrict__ cv,
                                                      const float* __restrict__ bias) {
    extern __shared__ char sm[];
    const uint32_t sbase = smem_to_u32(sm);
    const int tid = threadIdx.x, lane = tid & 31, wid = tid >> 5;
    const int warp_m = wid & 3, warp_n = wid >> 2;
    const int b = blockIdx.z, t0 = blockIdx.y * 256, s0 = blockIdx.x * 128;
    const size_t boff = (size_t)b * T_;

    float acc[4][4][4] = {};
    gemm_mainloop(acc, sbase, g_xwhi, g_xwlo, g_xhi, g_xlo,
                  boff + t0, boff + s0, tid, warp_m, warp_n, lane);

    // Per-lane cv/bias for its 8 s-columns
    float cvv[8], bsv[8];
    #pragma unroll
    for (int nf = 0; nf < 4; ++nf)
        #pragma unroll
        for (int e = 0; e < 2; ++e) {
            int c = s0 + warp_n * 32 + nf * 8 + (lane & 3) * 2 + e;
            cvv[nf * 2 + e] = cv[c];
            bsv[nf * 2 + e] = bias[c];
        }

    // Reduction staging in buf0 region (4 KB): last stage_mma reads buf 3,
    // so buf0 is dead for all warps past the final barrier.
    float* red = (float*)sm;   // [256][4]
    #pragma unroll
    for (int mf = 0; mf < 4; ++mf) {
        float p0 = 0.0f, p1 = 0.0f;
        #pragma unroll
        for (int nf = 0; nf < 4; ++nf)
            #pragma unroll
            for (int e = 0; e < 2; ++e) {
                p0 += cvv[nf*2+e] * fast_tanhf(acc[mf][nf][e]     + bsv[nf*2+e]);
                p1 += cvv[nf*2+e] * fast_tanhf(acc[mf][nf][2 + e] + bsv[nf*2+e]);
            }
        // reduce across the 4 lanes sharing a row
        p0 += __shfl_xor_sync(0xffffffffu, p0, 1);
        p0 += __shfl_xor_sync(0xffffffffu, p0, 2);
        p1 += __shfl_xor_sync(0xffffffffu, p1, 1);
        p1 += __shfl_xor_sync(0xffffffffu, p1, 2);
        if ((lane & 3) == 0) {
            int r = warp_m * 64 + mf * 16 + (lane >> 2);
            red[r * 4 + warp_n]       = p0;
            red[(r + 8) * 4 + warp_n] = p1;
        }
    }
    __syncthreads();
    if (tid < 256) {
        float s = red[tid * 4] + red[tid * 4 + 1] + red[tid * 4 + 2] + red[tid * 4 + 3];
        g_part[(boff + t0 + tid) * NS_ + blockIdx.x] = s;
    }
}

// ---------------------------------------------------------------------------
// Kernel 3: masked softmax over T per batch. grid = B, block = T.
// ---------------------------------------------------------------------------
__global__ __launch_bounds__(T_) void k_softmax(const unsigned char* __restrict__ mask,
                                                float* __restrict__ a_out) {
    const int b = blockIdx.x;
    const int t = threadIdx.x;
    __shared__ float sh[T_];

    float sc = 0.0f;
    #pragma unroll
    for (int j = 0; j < NS_; ++j)
        sc += g_part[((size_t)b * T_ + t) * NS_ + j];

    bool m;
    if (g_mask_is_byte) m = mask[(size_t)b * T_ + t] != 0;
    else                m = ((const int*)mask)[(size_t)b * T_ + t] != 0;

    const float NEG_INF = __int_as_float(0xff800000);
    float v = m ? sc : NEG_INF;

    sh[t] = v; __syncthreads();
    for (int off = T_ / 2; off > 0; off >>= 1) {
        if (t < off) sh[t] = fmaxf(sh[t], sh[t + off]);
        __syncthreads();
    }
    const float mx = sh[0];
    __syncthreads();

    float e = m ? expf(v - mx) : 0.0f;
    sh[t] = e; __syncthreads();
    for (int off = T_ / 2; off > 0; off >>= 1) {
        if (t < off) sh[t] += sh[t + off];
        __syncthreads();
    }
    float av = e * (1.0f / sh[0]);
    g_a[(size_t)b * T_ + t] = av;
    if (a_out) a_out[(size_t)b * T_ + t] = av;
}

// ---------------------------------------------------------------------------
// Kernel 4: out[b,d] = sum_t a[b,t] * x[b,t,d]
// ---------------------------------------------------------------------------
__global__ __launch_bounds__(128) void k_out(const float* __restrict__ x,
                                             float* __restrict__ out) {
    const int b = blockIdx.y;
    const int d = blockIdx.x * 128 + threadIdx.x;
    __shared__ float sa[T_];
    for (int t = threadIdx.x; t < T_; t += 128)
        sa[t] = g_a[(size_t)b * T_ + t];
    __syncthreads();

    float acc = 0.0f;
    const float* xb = x + (size_t)b * T_ * D_ + d;
    #pragma unroll 8
    for (int t = 0; t < T_; ++t)
        acc += sa[t] * xb[(size_t)t * D_];
    out[(size_t)b * D_ + d] = acc;
}

// ---------------------------------------------------------------------------
extern "C" void kernel_launch(void* const* d_in, const int* in_sizes, int n_in,
                              void* d_out, int out_size) {
    const float*         x    = (const float*)d_in[0];
    const unsigned char* mask = (const unsigned char*)d_in[1];
    const float*         w    = (const float*)d_in[2];
    const float*         cv   = (const float*)d_in[3];
    const float*         bias = (const float*)d_in[4];
    float* out = (float*)d_out;
    float* a_out = (out_size >= B_ * D_ + B_ * T_) ? out + (size_t)B_ * D_ : nullptr;

    cudaFuncSetAttribute(k_xw_tc,     cudaFuncAttributeMaxDynamicSharedMemorySize, SM_TOTAL);
    cudaFuncSetAttribute(k_scores_tc, cudaFuncAttributeMaxDynamicSharedMemorySize, SM_TOTAL);

    k_detect   <<<1, 1024>>>(mask);
    k_split_x  <<<(B_ * T_ * D_) / (4 * 256), 256>>>(x);
    k_split_wt <<<dim3(D_ / 32, D_ / 32), 1024>>>(w);
    k_xw_tc    <<<dim3(D_ / 128, (B_ * T_) / 256), 512, SM_TOTAL>>>();
    k_scores_tc<<<dim3(T_ / 128, T_ / 256, B_), 512, SM_TOTAL>>>(cv, bias);
    k_softmax  <<<B_, T_>>>(mask, a_out);
    k_out      <<<dim3(D_ / 128, B_), 128>>>(x, out);
}

// round 12
// speedup vs baseline: 1.4908x; 1.1381x over previous
#include <cuda_runtime.h>
#include <cuda_bf16.h>
#include <math.h>
#include <stdint.h>

#define B_  64
#define T_  512
#define D_  1024
#define NS_ (T_ / 128)          // s-tiles per row for score partials (=4)

// ---------------------------------------------------------------------------
// Device-global scratch (no allocation allowed)
// ---------------------------------------------------------------------------
__device__ __align__(16) __nv_bfloat16 g_xhi [(size_t)B_ * T_ * D_];
__device__ __align__(16) __nv_bfloat16 g_xlo [(size_t)B_ * T_ * D_];
__device__ __align__(16) __nv_bfloat16 g_wthi[(size_t)D_ * D_];   // W^T: [n][k]
__device__ __align__(16) __nv_bfloat16 g_wtlo[(size_t)D_ * D_];
__device__ __align__(16) __nv_bfloat16 g_xwhi[(size_t)B_ * T_ * D_];
__device__ __align__(16) __nv_bfloat16 g_xwlo[(size_t)B_ * T_ * D_];
__device__ float g_part[(size_t)B_ * T_ * NS_];
__device__ float g_a[(size_t)B_ * T_];
__device__ int   g_mask_is_byte;

__device__ __forceinline__ uint32_t smem_to_u32(const void* p) {
    uint32_t a;
    asm("{ .reg .u64 t; cvta.to.shared.u64 t, %1; cvt.u32.u64 %0, t; }"
        : "=r"(a) : "l"(p));
    return a;
}
__device__ __forceinline__ float fast_tanhf(float x) {
    float e = __expf(2.0f * x);
    return 1.0f - 2.0f / (e + 1.0f);
}
__device__ __forceinline__ uint32_t pack_bf16(float a, float b) {
    __nv_bfloat162 h = __floats2bfloat162_rn(a, b);
    return *(uint32_t*)&h;
}

// ---------------------------------------------------------------------------
// Tensor-core primitives (arch-agnostic: sm_80+ — valid on plain sm_103)
// ---------------------------------------------------------------------------
__device__ __forceinline__ void mma16816(float* c, const uint32_t* a, const uint32_t* b) {
    asm volatile("mma.sync.aligned.m16n8k16.row.col.f32.bf16.bf16.f32 "
                 "{%0,%1,%2,%3}, {%4,%5,%6,%7}, {%8,%9}, {%0,%1,%2,%3};"
                 : "+f"(c[0]), "+f"(c[1]), "+f"(c[2]), "+f"(c[3])
                 : "r"(a[0]), "r"(a[1]), "r"(a[2]), "r"(a[3]), "r"(b[0]), "r"(b[1]));
}
__device__ __forceinline__ void ldsm_x4(uint32_t* r, uint32_t addr) {
    asm volatile("ldmatrix.sync.aligned.m8n8.x4.shared.b16 {%0,%1,%2,%3}, [%4];"
                 : "=r"(r[0]), "=r"(r[1]), "=r"(r[2]), "=r"(r[3]) : "r"(addr));
}
__device__ __forceinline__ void cp_async16(uint32_t smem, const void* gmem) {
    asm volatile("cp.async.cg.shared.global [%0], [%1], 16;" :: "r"(smem), "l"(gmem));
}
#define CP_COMMIT()  asm volatile("cp.async.commit_group;" ::: "memory")
#define CP_WAIT(n)   asm volatile("cp.async.wait_group %0;" :: "n"(n) : "memory")

// ---------------------------------------------------------------------------
// Shared tile layout (R9 best): hi/lo merged side-by-side into 128B rows.
// Row r = [HI(r,k0:32) | LO(r,k0:32)] = 8 x 16B chunks; chunk pc lives at
// physical (pc ^ (r&7)) -> conflict-free ldmatrix AND cp.async stores.
// THREE buffers now: loads issued 2 stages ahead, CP_WAIT(1) gives each
// load group ~2 full MMA windows to land instead of R9's marginal 1.
// ---------------------------------------------------------------------------
#define OFF_A    0
#define OFF_B    16384
#define BUF_SZ   32768
#define SM_TOTAL (3 * BUF_SZ)   // 96 KB dynamic (2 CTAs/SM = 192 KB <= 228)
#define STAGES   (D_ / 32)      // 32

// Load one merged 128-row x 128B tile (16KB) from hi/lo sources:
// 1024 chunks, 4 per thread; pc = tid&7 fixed -> loop-invariant src pointer.
__device__ __forceinline__ void ld_tile(uint32_t sbase,
                                        const __nv_bfloat16* __restrict__ hiSrc,
                                        const __nv_bfloat16* __restrict__ loSrc,
                                        size_t row0, int k0, int tid) {
    const int pc = tid & 7;              // part = pc>>2, c = pc&3
    const int c  = pc & 3;
    const __nv_bfloat16* src = (pc >= 4) ? loSrc : hiSrc;
    #pragma unroll
    for (int i = 0; i < 4; ++i) {
        int r = (tid >> 3) + 32 * i;
        cp_async16(sbase + r * 128 + ((pc ^ (r & 7)) << 4),
                   src + (row0 + r) * D_ + k0 + c * 8);
    }
}

__device__ __forceinline__ void ld_stage(uint32_t sbuf,
                                         const __nv_bfloat16* aHi, const __nv_bfloat16* aLo,
                                         const __nv_bfloat16* bHi, const __nv_bfloat16* bLo,
                                         size_t arow0, size_t brow0, int k0, int tid) {
    ld_tile(sbuf + OFF_A, aHi, aLo, arow0, k0, tid);
    ld_tile(sbuf + OFF_B, bHi, bLo, brow0, k0, tid);
    CP_COMMIT();
}

// ldmatrix address: 16x16 frag (4 8x8 matrices) at (rowbase, logical pcbase).
__device__ __forceinline__ uint32_t frag_addr(uint32_t base, int rowbase, int pcbase, int lane) {
    int grp = lane >> 3, rin = lane & 7;
    int row = rowbase + ((grp & 1) << 3) + rin;
    int pc  = pcbase + (grp >> 1);
    return base + row * 128 + ((pc ^ (row & 7)) << 4);
}

// One stage (K=32) of 3-product split MMA into acc[4][4][4].
__device__ __forceinline__ void stage_mma(float acc[4][4][4], uint32_t sbuf,
                                          int warp_m, int warp_n, int lane) {
    #pragma unroll
    for (int ks = 0; ks < 2; ++ks) {
        uint32_t ahi[4][4], alo[4][4];
        #pragma unroll
        for (int mf = 0; mf < 4; ++mf) {
            ldsm_x4(ahi[mf], frag_addr(sbuf + OFF_A, warp_m * 64 + mf * 16, ks * 2,     lane));
            ldsm_x4(alo[mf], frag_addr(sbuf + OFF_A, warp_m * 64 + mf * 16, 4 + ks * 2, lane));
        }
        uint32_t bhi[4][2], blo[4][2];
        #pragma unroll
        for (int p = 0; p < 2; ++p) {
            uint32_t r[4];
            ldsm_x4(r, frag_addr(sbuf + OFF_B, warp_n * 32 + p * 16, ks * 2, lane));
            bhi[2*p][0] = r[0]; bhi[2*p][1] = r[2];
            bhi[2*p+1][0] = r[1]; bhi[2*p+1][1] = r[3];
            ldsm_x4(r, frag_addr(sbuf + OFF_B, warp_n * 32 + p * 16, 4 + ks * 2, lane));
            blo[2*p][0] = r[0]; blo[2*p][1] = r[2];
            blo[2*p+1][0] = r[1]; blo[2*p+1][1] = r[3];
        }
        #pragma unroll
        for (int mf = 0; mf < 4; ++mf)
            #pragma unroll
            for (int nf = 0; nf < 4; ++nf)
                mma16816(acc[mf][nf], ahi[mf], bhi[nf]);
        #pragma unroll
        for (int mf = 0; mf < 4; ++mf)
            #pragma unroll
            for (int nf = 0; nf < 4; ++nf)
                mma16816(acc[mf][nf], ahi[mf], blo[nf]);
        #pragma unroll
        for (int mf = 0; mf < 4; ++mf)
            #pragma unroll
            for (int nf = 0; nf < 4; ++nf)
                mma16816(acc[mf][nf], alo[mf], bhi[nf]);
    }
}

// Mainloop: 3 buffers with COMPILE-TIME offsets (manual unroll-3), loads
// issued 2 stages ahead, CP_WAIT(1) at each stage top (group s guaranteed
// complete; group s+1 still in flight). Single barrier per stage: at stage s
// all warps are past mma(s-1), the only reader of the buffer loads(s+2)
// overwrite ((s+2)%3 == (s-1)%3).
__device__ __forceinline__ void gemm_mainloop(float acc[4][4][4], uint32_t sbase,
                                              const __nv_bfloat16* aHi, const __nv_bfloat16* aLo,
                                              const __nv_bfloat16* bHi, const __nv_bfloat16* bLo,
                                              size_t arow0, size_t brow0,
                                              int tid, int warp_m, int warp_n, int lane) {
    const uint32_t b0 = sbase, b1 = sbase + BUF_SZ, b2 = sbase + 2 * BUF_SZ;
    ld_stage(b0, aHi, aLo, bHi, bLo, arow0, brow0, 0,  tid);
    ld_stage(b1, aHi, aLo, bHi, bLo, arow0, brow0, 32, tid);
    #pragma unroll 1
    for (int s = 0; s < 30; s += 3) {
        CP_WAIT(1);
        __syncthreads();
        ld_stage(b2, aHi, aLo, bHi, bLo, arow0, brow0, (s + 2) * 32, tid);
        stage_mma(acc, b0, warp_m, warp_n, lane);
        CP_WAIT(1);
        __syncthreads();
        ld_stage(b0, aHi, aLo, bHi, bLo, arow0, brow0, (s + 3) * 32, tid);
        stage_mma(acc, b1, warp_m, warp_n, lane);
        CP_WAIT(1);
        __syncthreads();
        ld_stage(b1, aHi, aLo, bHi, bLo, arow0, brow0, (s + 4) * 32, tid);
        stage_mma(acc, b2, warp_m, warp_n, lane);
    }
    // Tail: stages 30 (buf0) and 31 (buf1); all 32 load groups already issued.
    CP_WAIT(1);
    __syncthreads();
    stage_mma(acc, b0, warp_m, warp_n, lane);
    CP_WAIT(0);
    __syncthreads();
    stage_mma(acc, b1, warp_m, warp_n, lane);
}

// ---------------------------------------------------------------------------
// Kernel 0: mask dtype detection (byte-bool vs int32)
// ---------------------------------------------------------------------------
__global__ void k_detect(const unsigned char* __restrict__ m) {
    __shared__ int found;
    if (threadIdx.x == 0) found = 0;
    __syncthreads();
    int f = 0;
    for (int i = threadIdx.x; i < B_ * T_; i += blockDim.x)
        if ((i & 3) != 0 && m[i] != 0) f = 1;
    if (f) atomicOr(&found, 1);
    __syncthreads();
    if (threadIdx.x == 0) g_mask_is_byte = found;
}

// ---------------------------------------------------------------------------
// Split x into bf16 hi/lo (4 floats per thread, vectorized).
// ---------------------------------------------------------------------------
__global__ __launch_bounds__(256) void k_split_x(const float* __restrict__ x) {
    size_t idx = (size_t)blockIdx.x * blockDim.x + threadIdx.x;
    float4 v = ((const float4*)x)[idx];
    float h0 = __bfloat162float(__float2bfloat16_rn(v.x));
    float h1 = __bfloat162float(__float2bfloat16_rn(v.y));
    float h2 = __bfloat162float(__float2bfloat16_rn(v.z));
    float h3 = __bfloat162float(__float2bfloat16_rn(v.w));
    ((uint2*)g_xhi)[idx] = make_uint2(pack_bf16(h0, h1), pack_bf16(h2, h3));
    ((uint2*)g_xlo)[idx] = make_uint2(pack_bf16(v.x - h0, v.y - h1),
                                      pack_bf16(v.z - h2, v.w - h3));
}

// ---------------------------------------------------------------------------
// Split + transpose W: g_wt*[n*D + k] = split(W[k*D + n])
// ---------------------------------------------------------------------------
__global__ __launch_bounds__(1024) void k_split_wt(const float* __restrict__ w) {
    __shared__ float t[32][33];
    int tx = threadIdx.x & 31, ty = threadIdx.x >> 5;
    int k = blockIdx.y * 32 + ty, n = blockIdx.x * 32 + tx;
    t[ty][tx] = w[(size_t)k * D_ + n];
    __syncthreads();
    float v = t[tx][ty];  // = W[by*32+tx][bx*32+ty]
    int nn = blockIdx.x * 32 + ty, kk = blockIdx.y * 32 + tx;
    float h = __bfloat162float(__float2bfloat16_rn(v));
    g_wthi[(size_t)nn * D_ + kk] = __float2bfloat16_rn(v);
    g_wtlo[(size_t)nn * D_ + kk] = __float2bfloat16_rn(v - h);
}

// ---------------------------------------------------------------------------
// Kernel 1: xw = x @ W. Tile 128x128, grid (D/128, B*T/128), 256 threads.
// __launch_bounds__(256, 2) pins regs <= 128 so 2 CTAs/SM is guaranteed.
// ---------------------------------------------------------------------------
__global__ __launch_bounds__(256, 2) void k_xw_tc() {
    extern __shared__ char sm[];
    const uint32_t sbase = smem_to_u32(sm);
    const int tid = threadIdx.x, lane = tid & 31, wid = tid >> 5;
    const int warp_m = wid & 1, warp_n = wid >> 1;
    const size_t m0 = (size_t)blockIdx.y * 128;
    const size_t n0 = (size_t)blockIdx.x * 128;

    float acc[4][4][4] = {};
    gemm_mainloop(acc, sbase, g_xhi, g_xlo, g_wthi, g_wtlo,
                  m0, n0, tid, warp_m, warp_n, lane);

    #pragma unroll
    for (int mf = 0; mf < 4; ++mf) {
        size_t r0 = m0 + warp_m * 64 + mf * 16 + (lane >> 2);
        #pragma unroll
        for (int nf = 0; nf < 4; ++nf) {
            size_t c = n0 + warp_n * 32 + nf * 8 + (lane & 3) * 2;
            float v0 = acc[mf][nf][0], v1 = acc[mf][nf][1];
            float v2 = acc[mf][nf][2], v3 = acc[mf][nf][3];
            float h0 = __bfloat162float(__float2bfloat16_rn(v0));
            float h1 = __bfloat162float(__float2bfloat16_rn(v1));
            float h2 = __bfloat162float(__float2bfloat16_rn(v2));
            float h3 = __bfloat162float(__float2bfloat16_rn(v3));
            *(uint32_t*)(g_xwhi + r0 * D_ + c)       = pack_bf16(h0, h1);
            *(uint32_t*)(g_xwlo + r0 * D_ + c)       = pack_bf16(v0 - h0, v1 - h1);
            *(uint32_t*)(g_xwhi + (r0 + 8) * D_ + c) = pack_bf16(h2, h3);
            *(uint32_t*)(g_xwlo + (r0 + 8) * D_ + c) = pack_bf16(v2 - h2, v3 - h3);
        }
    }
}

// ---------------------------------------------------------------------------
// Kernel 2: eij tile = xw_b[t0:+128] @ x_b[s0:+128]^T with fused
// cv*tanh(e+bias) reduction over s. grid (T/128, T/128, B).
// ---------------------------------------------------------------------------
__global__ __launch_bounds__(256, 2) void k_scores_tc(const float* __restrict__ cv,
                                                      const float* __restrict__ bias) {
    extern __shared__ char sm[];
    const uint32_t sbase = smem_to_u32(sm);
    const int tid = threadIdx.x, lane = tid & 31, wid = tid >> 5;
    const int warp_m = wid & 1, warp_n = wid >> 1;
    const int b = blockIdx.z, t0 = blockIdx.y * 128, s0 = blockIdx.x * 128;
    const size_t boff = (size_t)b * T_;

    float acc[4][4][4] = {};
    gemm_mainloop(acc, sbase, g_xwhi, g_xwlo, g_xhi, g_xlo,
                  boff + t0, boff + s0, tid, warp_m, warp_n, lane);

    // Per-lane cv/bias for its 8 s-columns
    float cvv[8], bsv[8];
    #pragma unroll
    for (int nf = 0; nf < 4; ++nf)
        #pragma unroll
        for (int e = 0; e < 2; ++e) {
            int c = s0 + warp_n * 32 + nf * 8 + (lane & 3) * 2 + e;
            cvv[nf * 2 + e] = cv[c];
            bsv[nf * 2 + e] = bias[c];
        }

    // Reduction staging in buf0 region: after the final barrier (top of
    // stage 31) no warp reads buf0 again (stage 31 reads buf1 only).
    float* red = (float*)sm;
    #pragma unroll
    for (int mf = 0; mf < 4; ++mf) {
        float p0 = 0.0f, p1 = 0.0f;
        #pragma unroll
        for (int nf = 0; nf < 4; ++nf)
            #pragma unroll
            for (int e = 0; e < 2; ++e) {
                p0 += cvv[nf*2+e] * fast_tanhf(acc[mf][nf][e]     + bsv[nf*2+e]);
                p1 += cvv[nf*2+e] * fast_tanhf(acc[mf][nf][2 + e] + bsv[nf*2+e]);
            }
        // reduce across the 4 lanes sharing a row
        p0 += __shfl_xor_sync(0xffffffffu, p0, 1);
        p0 += __shfl_xor_sync(0xffffffffu, p0, 2);
        p1 += __shfl_xor_sync(0xffffffffu, p1, 1);
        p1 += __shfl_xor_sync(0xffffffffu, p1, 2);
        if ((lane & 3) == 0) {
            int r = warp_m * 64 + mf * 16 + (lane >> 2);
            red[r * 4 + warp_n]       = p0;
            red[(r + 8) * 4 + warp_n] = p1;
        }
    }
    __syncthreads();
    if (tid < 128) {
        float s = red[tid * 4] + red[tid * 4 + 1] + red[tid * 4 + 2] + red[tid * 4 + 3];
        g_part[(boff + t0 + tid) * NS_ + blockIdx.x] = s;
    }
}

// ---------------------------------------------------------------------------
// Kernel 3: masked softmax over T per batch. grid = B, block = T.
// ---------------------------------------------------------------------------
__global__ __launch_bounds__(T_) void k_softmax(const unsigned char* __restrict__ mask,
                                                float* __restrict__ a_out) {
    const int b = blockIdx.x;
    const int t = threadIdx.x;
    __shared__ float sh[T_];

    float sc = 0.0f;
    #pragma unroll
    for (int j = 0; j < NS_; ++j)
        sc += g_part[((size_t)b * T_ + t) * NS_ + j];

    bool m;
    if (g_mask_is_byte) m = mask[(size_t)b * T_ + t] != 0;
    else                m = ((const int*)mask)[(size_t)b * T_ + t] != 0;

    const float NEG_INF = __int_as_float(0xff800000);
    float v = m ? sc : NEG_INF;

    sh[t] = v; __syncthreads();
    for (int off = T_ / 2; off > 0; off >>= 1) {
        if (t < off) sh[t] = fmaxf(sh[t], sh[t + off]);
        __syncthreads();
    }
    const float mx = sh[0];
    __syncthreads();

    float e = m ? expf(v - mx) : 0.0f;
    sh[t] = e; __syncthreads();
    for (int off = T_ / 2; off > 0; off >>= 1) {
        if (t < off) sh[t] += sh[t + off];
        __syncthreads();
    }
    float av = e * (1.0f / sh[0]);
    g_a[(size_t)b * T_ + t] = av;
    if (a_out) a_out[(size_t)b * T_ + t] = av;
}

// ---------------------------------------------------------------------------
// Kernel 4: out[b,d] = sum_t a[b,t] * x[b,t,d]
// ---------------------------------------------------------------------------
__global__ __launch_bounds__(128) void k_out(const float* __restrict__ x,
                                             float* __restrict__ out) {
    const int b = blockIdx.y;
    const int d = blockIdx.x * 128 + threadIdx.x;
    __shared__ float sa[T_];
    for (int t = threadIdx.x; t < T_; t += 128)
        sa[t] = g_a[(size_t)b * T_ + t];
    __syncthreads();

    float acc = 0.0f;
    const float* xb = x + (size_t)b * T_ * D_ + d;
    #pragma unroll 8
    for (int t = 0; t < T_; ++t)
        acc += sa[t] * xb[(size_t)t * D_];
    out[(size_t)b * D_ + d] = acc;
}

// ---------------------------------------------------------------------------
extern "C" void kernel_launch(void* const* d_in, const int* in_sizes, int n_in,
                              void* d_out, int out_size) {
    const float*         x    = (const float*)d_in[0];
    const unsigned char* mask = (const unsigned char*)d_in[1];
    const float*         w    = (const float*)d_in[2];
    const float*         cv   = (const float*)d_in[3];
    const float*         bias = (const float*)d_in[4];
    float* out = (float*)d_out;
    float* a_out = (out_size >= B_ * D_ + B_ * T_) ? out + (size_t)B_ * D_ : nullptr;

    cudaFuncSetAttribute(k_xw_tc,     cudaFuncAttributeMaxDynamicSharedMemorySize, SM_TOTAL);
    cudaFuncSetAttribute(k_scores_tc, cudaFuncAttributeMaxDynamicSharedMemorySize, SM_TOTAL);

    k_detect   <<<1, 1024>>>(mask);
    k_split_x  <<<(B_ * T_ * D_) / (4 * 256), 256>>>(x);
    k_split_wt <<<dim3(D_ / 32, D_ / 32), 1024>>>(w);
    k_xw_tc    <<<dim3(D_ / 128, (B_ * T_) / 128), 256, SM_TOTAL>>>();
    k_scores_tc<<<dim3(T_ / 128, T_ / 128, B_), 256, SM_TOTAL>>>(cv, bias);
    k_softmax  <<<B_, T_>>>(mask, a_out);
    k_out      <<<dim3(D_ / 128, B_), 128>>>(x, out);
}

// round 16
// speedup vs baseline: 1.4969x; 1.0041x over previous
#include <cuda_runtime.h>
#include <cuda_bf16.h>
#include <math.h>
#include <stdint.h>

#define B_  64
#define T_  512
#define D_  1024
#define NS_ (T_ / 128)          // s-tiles per row for score partials (=4)

// ---------------------------------------------------------------------------
// Device-global scratch (no allocation allowed)
// ---------------------------------------------------------------------------
__device__ __align__(16) __nv_bfloat16 g_xhi [(size_t)B_ * T_ * D_];
__device__ __align__(16) __nv_bfloat16 g_xlo [(size_t)B_ * T_ * D_];
__device__ __align__(16) __nv_bfloat16 g_wthi[(size_t)D_ * D_];   // W^T: [n][k]
__device__ __align__(16) __nv_bfloat16 g_wtlo[(size_t)D_ * D_];
__device__ __align__(16) __nv_bfloat16 g_xwhi[(size_t)B_ * T_ * D_];
__device__ __align__(16) __nv_bfloat16 g_xwlo[(size_t)B_ * T_ * D_];
__device__ float g_part[(size_t)B_ * T_ * NS_];
__device__ float g_a[(size_t)B_ * T_];
__device__ int   g_mask_is_byte;

__device__ __forceinline__ uint32_t smem_to_u32(const void* p) {
    uint32_t a;
    asm("{ .reg .u64 t; cvta.to.shared.u64 t, %1; cvt.u32.u64 %0, t; }"
        : "=r"(a) : "l"(p));
    return a;
}
__device__ __forceinline__ float fast_tanhf(float x) {
    float e = __expf(2.0f * x);
    return 1.0f - 2.0f / (e + 1.0f);
}
__device__ __forceinline__ uint32_t pack_bf16(float a, float b) {
    __nv_bfloat162 h = __floats2bfloat162_rn(a, b);
    return *(uint32_t*)&h;
}

// ---------------------------------------------------------------------------
// Tensor-core primitives (arch-agnostic: sm_80+ — valid on plain sm_103)
// ---------------------------------------------------------------------------
__device__ __forceinline__ void mma16816(float* c, const uint32_t* a, const uint32_t* b) {
    asm volatile("mma.sync.aligned.m16n8k16.row.col.f32.bf16.bf16.f32 "
                 "{%0,%1,%2,%3}, {%4,%5,%6,%7}, {%8,%9}, {%0,%1,%2,%3};"
                 : "+f"(c[0]), "+f"(c[1]), "+f"(c[2]), "+f"(c[3])
                 : "r"(a[0]), "r"(a[1]), "r"(a[2]), "r"(a[3]), "r"(b[0]), "r"(b[1]));
}
__device__ __forceinline__ void ldsm_x4(uint32_t* r, uint32_t addr) {
    asm volatile("ldmatrix.sync.aligned.m8n8.x4.shared.b16 {%0,%1,%2,%3}, [%4];"
                 : "=r"(r[0]), "=r"(r[1]), "=r"(r[2]), "=r"(r[3]) : "r"(addr));
}
__device__ __forceinline__ void cp_async16(uint32_t smem, const void* gmem) {
    asm volatile("cp.async.cg.shared.global [%0], [%1], 16;" :: "r"(smem), "l"(gmem));
}
#define CP_COMMIT()  asm volatile("cp.async.commit_group;" ::: "memory")
#define CP_WAIT(n)   asm volatile("cp.async.wait_group %0;" :: "n"(n) : "memory")

// ---------------------------------------------------------------------------
// Shared tile layout (R12, proven): hi/lo merged side-by-side into 128B rows.
// Row r = [HI(r,k0:32) | LO(r,k0:32)] = 8 x 16B chunks; chunk pc lives at
// physical (pc ^ (r&7)) -> conflict-free ldmatrix AND cp.async stores.
// THREE buffers, loads issued 2 stages ahead. Stage order is
// CP_WAIT -> __syncthreads -> ld -> mma: the wait-THEN-barrier sequence is
// load-bearing (wait_group is per-thread; the barrier makes ALL threads'
// group-s copies visible before any ldmatrix). Do not reorder.
// ---------------------------------------------------------------------------
#define OFF_A    0
#define OFF_B    16384
#define BUF_SZ   32768
#define SM_TOTAL (3 * BUF_SZ)   // 96 KB dynamic (2 CTAs/SM = 192 KB <= 228)
#define STAGES   (D_ / 32)      // 32

// Load one merged 128-row x 128B tile (16KB) from hi/lo sources:
// 1024 chunks, 4 per thread; pc = tid&7 fixed -> loop-invariant src pointer.
__device__ __forceinline__ void ld_tile(uint32_t sbase,
                                        const __nv_bfloat16* __restrict__ hiSrc,
                                        const __nv_bfloat16* __restrict__ loSrc,
                                        size_t row0, int k0, int tid) {
    const int pc = tid & 7;              // part = pc>>2, c = pc&3
    const int c  = pc & 3;
    const __nv_bfloat16* src = (pc >= 4) ? loSrc : hiSrc;
    #pragma unroll
    for (int i = 0; i < 4; ++i) {
        int r = (tid >> 3) + 32 * i;
        cp_async16(sbase + r * 128 + ((pc ^ (r & 7)) << 4),
                   src + (row0 + r) * D_ + k0 + c * 8);
    }
}

__device__ __forceinline__ void ld_stage(uint32_t sbuf,
                                         const __nv_bfloat16* aHi, const __nv_bfloat16* aLo,
                                         const __nv_bfloat16* bHi, const __nv_bfloat16* bLo,
                                         size_t arow0, size_t brow0, int k0, int tid) {
    ld_tile(sbuf + OFF_A, aHi, aLo, arow0, k0, tid);
    ld_tile(sbuf + OFF_B, bHi, bLo, brow0, k0, tid);
    CP_COMMIT();
}

// ldmatrix address: 16x16 frag (4 8x8 matrices) at (rowbase, logical pcbase).
__device__ __forceinline__ uint32_t frag_addr(uint32_t base, int rowbase, int pcbase, int lane) {
    int grp = lane >> 3, rin = lane & 7;
    int row = rowbase + ((grp & 1) << 3) + rin;
    int pc  = pcbase + (grp >> 1);
    return base + row * 128 + ((pc ^ (row & 7)) << 4);
}

// One stage (K=32) of 3-product split MMA into acc[4][4][4].
__device__ __forceinline__ void stage_mma(float acc[4][4][4], uint32_t sbuf,
                                          int warp_m, int warp_n, int lane) {
    #pragma unroll
    for (int ks = 0; ks < 2; ++ks) {
        uint32_t ahi[4][4], alo[4][4];
        #pragma unroll
        for (int mf = 0; mf < 4; ++mf) {
            ldsm_x4(ahi[mf], frag_addr(sbuf + OFF_A, warp_m * 64 + mf * 16, ks * 2,     lane));
            ldsm_x4(alo[mf], frag_addr(sbuf + OFF_A, warp_m * 64 + mf * 16, 4 + ks * 2, lane));
        }
        uint32_t bhi[4][2], blo[4][2];
        #pragma unroll
        for (int p = 0; p < 2; ++p) {
            uint32_t r[4];
            ldsm_x4(r, frag_addr(sbuf + OFF_B, warp_n * 32 + p * 16, ks * 2, lane));
            bhi[2*p][0] = r[0]; bhi[2*p][1] = r[2];
            bhi[2*p+1][0] = r[1]; bhi[2*p+1][1] = r[3];
            ldsm_x4(r, frag_addr(sbuf + OFF_B, warp_n * 32 + p * 16, 4 + ks * 2, lane));
            blo[2*p][0] = r[0]; blo[2*p][1] = r[2];
            blo[2*p+1][0] = r[1]; blo[2*p+1][1] = r[3];
        }
        #pragma unroll
        for (int mf = 0; mf < 4; ++mf)
            #pragma unroll
            for (int nf = 0; nf < 4; ++nf)
                mma16816(acc[mf][nf], ahi[mf], bhi[nf]);
        #pragma unroll
        for (int mf = 0; mf < 4; ++mf)
            #pragma unroll
            for (int nf = 0; nf < 4; ++nf)
                mma16816(acc[mf][nf], ahi[mf], blo[nf]);
        #pragma unroll
        for (int mf = 0; mf < 4; ++mf)
            #pragma unroll
            for (int nf = 0; nf < 4; ++nf)
                mma16816(acc[mf][nf], alo[mf], bhi[nf]);
    }
}

// Mainloop (R12, proven correct): 3 buffers with compile-time offsets,
// loads issued 2 stages ahead. Stage s:
//   CP_WAIT(1)     (my group-s copies done; group s+1 in flight)
//   __syncthreads  (ALL threads' group-s copies visible; all warps past
//                   mma(s-1) -> buffer (s+2)%3 == (s-1)%3 is dead)
//   ld_stage(s+2)  (issued before mma -> off the critical path)
//   stage_mma(s)
__device__ __forceinline__ void gemm_mainloop(float acc[4][4][4], uint32_t sbase,
                                              const __nv_bfloat16* aHi, const __nv_bfloat16* aLo,
                                              const __nv_bfloat16* bHi, const __nv_bfloat16* bLo,
                                              size_t arow0, size_t brow0,
                                              int tid, int warp_m, int warp_n, int lane) {
    const uint32_t b0 = sbase, b1 = sbase + BUF_SZ, b2 = sbase + 2 * BUF_SZ;
    ld_stage(b0, aHi, aLo, bHi, bLo, arow0, brow0, 0,  tid);
    ld_stage(b1, aHi, aLo, bHi, bLo, arow0, brow0, 32, tid);
    #pragma unroll 1
    for (int s = 0; s < 30; s += 3) {
        CP_WAIT(1);
        __syncthreads();
        ld_stage(b2, aHi, aLo, bHi, bLo, arow0, brow0, (s + 2) * 32, tid);
        stage_mma(acc, b0, warp_m, warp_n, lane);
        CP_WAIT(1);
        __syncthreads();
        ld_stage(b0, aHi, aLo, bHi, bLo, arow0, brow0, (s + 3) * 32, tid);
        stage_mma(acc, b1, warp_m, warp_n, lane);
        CP_WAIT(1);
        __syncthreads();
        ld_stage(b1, aHi, aLo, bHi, bLo, arow0, brow0, (s + 4) * 32, tid);
        stage_mma(acc, b2, warp_m, warp_n, lane);
    }
    // Tail: stages 30 (buf0) and 31 (buf1); all 32 load groups already issued.
    CP_WAIT(1);
    __syncthreads();
    stage_mma(acc, b0, warp_m, warp_n, lane);
    CP_WAIT(0);
    __syncthreads();
    stage_mma(acc, b1, warp_m, warp_n, lane);
}

// ---------------------------------------------------------------------------
// Kernel: split x into bf16 hi/lo (4 floats per thread, vectorized).
// Block 0 additionally detects the mask dtype (byte-bool vs int32).
// ---------------------------------------------------------------------------
__global__ __launch_bounds__(256) void k_split_x(const float* __restrict__ x,
                                                 const unsigned char* __restrict__ mask) {
    if (blockIdx.x == 0) {
        __shared__ int found;
        if (threadIdx.x == 0) found = 0;
        __syncthreads();
        int f = 0;
        for (int i = threadIdx.x; i < B_ * T_; i += blockDim.x)
            if ((i & 3) != 0 && mask[i] != 0) f = 1;
        if (f) atomicOr(&found, 1);
        __syncthreads();
        if (threadIdx.x == 0) g_mask_is_byte = found;
    }
    size_t idx = (size_t)blockIdx.x * blockDim.x + threadIdx.x;
    float4 v = ((const float4*)x)[idx];
    float h0 = __bfloat162float(__float2bfloat16_rn(v.x));
    float h1 = __bfloat162float(__float2bfloat16_rn(v.y));
    float h2 = __bfloat162float(__float2bfloat16_rn(v.z));
    float h3 = __bfloat162float(__float2bfloat16_rn(v.w));
    ((uint2*)g_xhi)[idx] = make_uint2(pack_bf16(h0, h1), pack_bf16(h2, h3));
    ((uint2*)g_xlo)[idx] = make_uint2(pack_bf16(v.x - h0, v.y - h1),
                                      pack_bf16(v.z - h2, v.w - h3));
}

// ---------------------------------------------------------------------------
// Split + transpose W: g_wt*[n*D + k] = split(W[k*D + n])
// ---------------------------------------------------------------------------
__global__ __launch_bounds__(1024) void k_split_wt(const float* __restrict__ w) {
    __shared__ float t[32][33];
    int tx = threadIdx.x & 31, ty = threadIdx.x >> 5;
    int k = blockIdx.y * 32 + ty, n = blockIdx.x * 32 + tx;
    t[ty][tx] = w[(size_t)k * D_ + n];
    __syncthreads();
    float v = t[tx][ty];  // = W[by*32+tx][bx*32+ty]
    int nn = blockIdx.x * 32 + ty, kk = blockIdx.y * 32 + tx;
    float h = __bfloat162float(__float2bfloat16_rn(v));
    g_wthi[(size_t)nn * D_ + kk] = __float2bfloat16_rn(v);
    g_wtlo[(size_t)nn * D_ + kk] = __float2bfloat16_rn(v - h);
}

// ---------------------------------------------------------------------------
// Kernel 1: xw = x @ W. Tile 128x128, grid (D/128, B*T/128), 256 threads.
// __launch_bounds__(256, 2) pins regs <= 128 so 2 CTAs/SM is guaranteed.
// ---------------------------------------------------------------------------
__global__ __launch_bounds__(256, 2) void k_xw_tc() {
    extern __shared__ char sm[];
    const uint32_t sbase = smem_to_u32(sm);
    const int tid = threadIdx.x, lane = tid & 31, wid = tid >> 5;
    const int warp_m = wid & 1, warp_n = wid >> 1;
    const size_t m0 = (size_t)blockIdx.y * 128;
    const size_t n0 = (size_t)blockIdx.x * 128;

    float acc[4][4][4] = {};
    gemm_mainloop(acc, sbase, g_xhi, g_xlo, g_wthi, g_wtlo,
                  m0, n0, tid, warp_m, warp_n, lane);

    #pragma unroll
    for (int mf = 0; mf < 4; ++mf) {
        size_t r0 = m0 + warp_m * 64 + mf * 16 + (lane >> 2);
        #pragma unroll
        for (int nf = 0; nf < 4; ++nf) {
            size_t c = n0 + warp_n * 32 + nf * 8 + (lane & 3) * 2;
            float v0 = acc[mf][nf][0], v1 = acc[mf][nf][1];
            float v2 = acc[mf][nf][2], v3 = acc[mf][nf][3];
            float h0 = __bfloat162float(__float2bfloat16_rn(v0));
            float h1 = __bfloat162float(__float2bfloat16_rn(v1));
            float h2 = __bfloat162float(__float2bfloat16_rn(v2));
            float h3 = __bfloat162float(__float2bfloat16_rn(v3));
            *(uint32_t*)(g_xwhi + r0 * D_ + c)       = pack_bf16(h0, h1);
            *(uint32_t*)(g_xwlo + r0 * D_ + c)       = pack_bf16(v0 - h0, v1 - h1);
            *(uint32_t*)(g_xwhi + (r0 + 8) * D_ + c) = pack_bf16(h2, h3);
            *(uint32_t*)(g_xwlo + (r0 + 8) * D_ + c) = pack_bf16(v2 - h2, v3 - h3);
        }
    }
}

// ---------------------------------------------------------------------------
// Kernel 2: eij tile = xw_b[t0:+128] @ x_b[s0:+128]^T with fused
// cv*tanh(e+bias) reduction over s. grid (T/128, T/128, B).
// ---------------------------------------------------------------------------
__global__ __launch_bounds__(256, 2) void k_scores_tc(const float* __restrict__ cv,
                                                      const float* __restrict__ bias) {
    extern __shared__ char sm[];
    const uint32_t sbase = smem_to_u32(sm);
    const int tid = threadIdx.x, lane = tid & 31, wid = tid >> 5;
    const int warp_m = wid & 1, warp_n = wid >> 1;
    const int b = blockIdx.z, t0 = blockIdx.y * 128, s0 = blockIdx.x * 128;
    const size_t boff = (size_t)b * T_;

    float acc[4][4][4] = {};
    gemm_mainloop(acc, sbase, g_xwhi, g_xwlo, g_xhi, g_xlo,
                  boff + t0, boff + s0, tid, warp_m, warp_n, lane);

    // Per-lane cv/bias for its 8 s-columns
    float cvv[8], bsv[8];
    #pragma unroll
    for (int nf = 0; nf < 4; ++nf)
        #pragma unroll
        for (int e = 0; e < 2; ++e) {
            int c = s0 + warp_n * 32 + nf * 8 + (lane & 3) * 2 + e;
            cvv[nf * 2 + e] = cv[c];
            bsv[nf * 2 + e] = bias[c];
        }

    // Reduction staging in buf0 region: after the final barrier no warp
    // reads buf0 again (stage 31 reads buf1 only).
    float* red = (float*)sm;
    #pragma unroll
    for (int mf = 0; mf < 4; ++mf) {
        float p0 = 0.0f, p1 = 0.0f;
        #pragma unroll
        for (int nf = 0; nf < 4; ++nf)
            #pragma unroll
            for (int e = 0; e < 2; ++e) {
                p0 += cvv[nf*2+e] * fast_tanhf(acc[mf][nf][e]     + bsv[nf*2+e]);
                p1 += cvv[nf*2+e] * fast_tanhf(acc[mf][nf][2 + e] + bsv[nf*2+e]);
            }
        // reduce across the 4 lanes sharing a row
        p0 += __shfl_xor_sync(0xffffffffu, p0, 1);
        p0 += __shfl_xor_sync(0xffffffffu, p0, 2);
        p1 += __shfl_xor_sync(0xffffffffu, p1, 1);
        p1 += __shfl_xor_sync(0xffffffffu, p1, 2);
        if ((lane & 3) == 0) {
            int r = warp_m * 64 + mf * 16 + (lane >> 2);
            red[r * 4 + warp_n]       = p0;
            red[(r + 8) * 4 + warp_n] = p1;
        }
    }
    __syncthreads();
    if (tid < 128) {
        float s = red[tid * 4] + red[tid * 4 + 1] + red[tid * 4 + 2] + red[tid * 4 + 3];
        g_part[(boff + t0 + tid) * NS_ + blockIdx.x] = s;
    }
}

// ---------------------------------------------------------------------------
// Kernel 3: masked softmax over T per batch. grid = B, block = T.
// ---------------------------------------------------------------------------
__global__ __launch_bounds__(T_) void k_softmax(const unsigned char* __restrict__ mask,
                                                float* __restrict__ a_out) {
    const int b = blockIdx.x;
    const int t = threadIdx.x;
    __shared__ float sh[T_];

    float sc = 0.0f;
    #pragma unroll
    for (int j = 0; j < NS_; ++j)
        sc += g_part[((size_t)b * T_ + t) * NS_ + j];

    bool m;
    if (g_mask_is_byte) m = mask[(size_t)b * T_ + t] != 0;
    else                m = ((const int*)mask)[(size_t)b * T_ + t] != 0;

    const float NEG_INF = __int_as_float(0xff800000);
    float v = m ? sc : NEG_INF;

    sh[t] = v; __syncthreads();
    for (int off = T_ / 2; off > 0; off >>= 1) {
        if (t < off) sh[t] = fmaxf(sh[t], sh[t + off]);
        __syncthreads();
    }
    const float mx = sh[0];
    __syncthreads();

    float e = m ? expf(v - mx) : 0.0f;
    sh[t] = e; __syncthreads();
    for (int off = T_ / 2; off > 0; off >>= 1) {
        if (t < off) sh[t] += sh[t + off];
        __syncthreads();
    }
    float av = e * (1.0f / sh[0]);
    g_a[(size_t)b * T_ + t] = av;
    if (a_out) a_out[(size_t)b * T_ + t] = av;
}

// ---------------------------------------------------------------------------
// Kernel 4: out[b,d] = sum_t a[b,t] * x[b,t,d]
// ---------------------------------------------------------------------------
__global__ __launch_bounds__(128) void k_out(const float* __restrict__ x,
                                             float* __restrict__ out) {
    const int b = blockIdx.y;
    const int d = blockIdx.x * 128 + threadIdx.x;
    __shared__ float sa[T_];
    for (int t = threadIdx.x; t < T_; t += 128)
        sa[t] = g_a[(size_t)b * T_ + t];
    __syncthreads();

    float acc = 0.0f;
    const float* xb = x + (size_t)b * T_ * D_ + d;
    #pragma unroll 8
    for (int t = 0; t < T_; ++t)
        acc += sa[t] * xb[(size_t)t * D_];
    out[(size_t)b * D_ + d] = acc;
}

// ---------------------------------------------------------------------------
extern "C" void kernel_launch(void* const* d_in, const int* in_sizes, int n_in,
                              void* d_out, int out_size) {
    const float*         x    = (const float*)d_in[0];
    const unsigned char* mask = (const unsigned char*)d_in[1];
    const float*         w    = (const float*)d_in[2];
    const float*         cv   = (const float*)d_in[3];
    const float*         bias = (const float*)d_in[4];
    float* out = (float*)d_out;
    float* a_out = (out_size >= B_ * D_ + B_ * T_) ? out + (size_t)B_ * D_ : nullptr;

    cudaFuncSetAttribute(k_xw_tc,     cudaFuncAttributeMaxDynamicSharedMemorySize, SM_TOTAL);
    cudaFuncSetAttribute(k_scores_tc, cudaFuncAttributeMaxDynamicSharedMemorySize, SM_TOTAL);

    k_split_x  <<<(B_ * T_ * D_) / (4 * 256), 256>>>(x, mask);
    k_split_wt <<<dim3(D_ / 32, D_ / 32), 1024>>>(w);
    k_xw_tc    <<<dim3(D_ / 128, (B_ * T_) / 128), 256, SM_TOTAL>>>();
    k_scores_tc<<<dim3(T_ / 128, T_ / 128, B_), 256, SM_TOTAL>>>(cv, bias);
    k_softmax  <<<B_, T_>>>(mask, a_out);
    k_out      <<<dim3(D_ / 128, B_), 128>>>(x, out);
}